// round 13
// baseline (speedup 1.0000x reference)
#include <cuda_runtime.h>
#include <cuda_bf16.h>
#include <stdint.h>

// Problem:
//   x:   (B, S) token ids in [0, V)   (B=512, S=1024, V=50257)
//   idf: (V,) fp32
//   out: (B, V) fp32 = (tf * idf) / rowsum(tf * idf)
//
// Fused single-kernel design (replaces memset + global-atomic scatter):
//   per row (one block): smem u16-packed tf histogram (100.5 KB, 2 blk/SM)
//   -> normalizer n = sum_s idf[x[row,s]] (block reduce)
//   -> streaming coalesced write-out of the full row: count * idf * inv_n.
// DRAM traffic = 103 MB writes (minimum) + 4 MB token reads; idf re-reads
// are L2-resident.

#define NTHREADS 1024

__inline__ __device__ float warp_reduce_sum(float v) {
    #pragma unroll
    for (int o = 16; o > 0; o >>= 1)
        v += __shfl_xor_sync(0xffffffffu, v, o);
    return v;
}

extern __shared__ unsigned int s_cnt[];   // ceil(vocab/2) u32 words (u16 pairs)

__global__ __launch_bounds__(NTHREADS, 2)
void tfidf_fused(const void* __restrict__ xv,
                 const float* __restrict__ idf,
                 float* __restrict__ out,
                 int seq, int vocab) {
    const int row = blockIdx.x;
    const int tid = threadIdx.x;
    const int nwords = (vocab + 1) >> 1;

    // --- index-width autodetect (int64 vs int32 token buffer) ---
    // Little-endian int64 values < 2^31 have zero high words at odd 32-bit
    // indices; P[4 real int32 tokens all == 0] ~ (1/50257)^4. Uniform branch.
    const int* xi = (const int*)xv;
    const bool is64 = (xi[1] == 0) & (xi[3] == 0) & (xi[5] == 0) & (xi[7] == 0);

    const long long* x64 = (const long long*)xv + (size_t)row * seq;
    const int*       x32 = xi + (size_t)row * seq;

    // 1) zero the smem histogram (25129 words / 1024 thr ~ 25 iters)
    for (int w = tid; w < nwords; w += NTHREADS)
        s_cnt[w] = 0u;
    __syncthreads();

    // 2) histogram tokens into packed u16 counts + gather idf for normalizer.
    //    u16 packing is safe: counts <= seq (1024) < 2^16, and a low-half
    //    increment can never carry into the high half.
    float partial = 0.0f;
    for (int s = tid; s < seq; s += NTHREADS) {
        int tok = is64 ? (int)x64[s] : x32[s];
        atomicAdd(&s_cnt[tok >> 1], 1u << ((tok & 1) * 16));
        partial += __ldg(idf + tok);
    }

    // 3) block reduction -> inv_n (32 warps)
    __shared__ float red[NTHREADS / 32];
    __shared__ float inv_n_sh;
    float ws = warp_reduce_sum(partial);
    const int lane = tid & 31;
    const int warp = tid >> 5;
    if (lane == 0) red[warp] = ws;
    __syncthreads();
    if (warp == 0) {
        float v = (lane < (NTHREADS / 32)) ? red[lane] : 0.0f;
        v = warp_reduce_sum(v);
        if (lane == 0) inv_n_sh = 1.0f / v;
    }
    __syncthreads();
    const float inv_n = inv_n_sh;

    // 4) streaming write-out of the entire row (zeros included) — coalesced
    //    STG.32 (row base is 4B-aligned only: vocab is odd). idf reads are
    //    coalesced and L2-resident.
    float* orow = out + (size_t)row * vocab;
    for (int v = tid; v < vocab; v += NTHREADS) {
        unsigned int pair = s_cnt[v >> 1];
        unsigned int cnt  = (v & 1) ? (pair >> 16) : (pair & 0xFFFFu);
        orow[v] = (float)cnt * __ldg(idf + v) * inv_n;
    }
}

extern "C" void kernel_launch(void* const* d_in, const int* in_sizes, int n_in,
                              void* d_out, int out_size) {
    (void)n_in;
    const void*  x   = d_in[0];                 // (B, S) tokens
    const float* idf = (const float*)d_in[1];   // (V,) fp32
    float*       out = (float*)d_out;           // (B, V) fp32

    const int vocab = in_sizes[1];              // V
    const int batch = out_size / vocab;         // B
    const int seq   = in_sizes[0] / batch;      // S

    const int smem_bytes = ((vocab + 1) / 2) * (int)sizeof(unsigned int);

    // opt-in to >48KB dynamic smem (idempotent; not a stream op, capture-safe)
    static int attr_done = 0;
    if (!attr_done) {
        cudaFuncSetAttribute(tfidf_fused,
                             cudaFuncAttributeMaxDynamicSharedMemorySize,
                             smem_bytes);
        attr_done = 1;
    }

    tfidf_fused<<<batch, NTHREADS, smem_bytes, 0>>>(x, idf, out, seq, vocab);
}

// round 14
// speedup vs baseline: 1.0010x; 1.0010x over previous
#include <cuda_runtime.h>
#include <cuda_bf16.h>
#include <stdint.h>

// Problem:
//   x:   (B, S) token ids in [0, V)   (B=512, S=1024, V=50257)
//   idf: (V,) fp32
//   out: (B, V) fp32 = (tf * idf) / rowsum(tf * idf)
//
// R14 design: the output is >=98% zeros, and zeros need no data.
//   per row (one block):
//     - smem u16-packed tf histogram of the 1024 tokens (100.5 KB)
//     - normalizer n = sum_s idf[x[row,s]]  (block reduce)
//     - DENSE phase: vectorized STG.128 zero-fill of the whole row (no loads)
//     - SPARSE phase: out[tok] = cnt[tok]*idf[tok]*inv_n for each token.
//       Duplicate tokens store the SAME value -> idempotent, no atomics.
//   __syncthreads() between phases orders the block's global stores.
// L2 traffic ~ 103 MB zero-writes + ~8 MB sparse/reads (vs 206 MB in R13).

#define NTHREADS 1024

__inline__ __device__ float warp_reduce_sum(float v) {
    #pragma unroll
    for (int o = 16; o > 0; o >>= 1)
        v += __shfl_xor_sync(0xffffffffu, v, o);
    return v;
}

extern __shared__ unsigned int s_cnt[];   // ceil(vocab/2) u32 (u16 pairs)

__global__ __launch_bounds__(NTHREADS, 2)
void tfidf_sparse(const void* __restrict__ xv,
                  const float* __restrict__ idf,
                  float* __restrict__ out,
                  int seq, int vocab) {
    const int row = blockIdx.x;
    const int tid = threadIdx.x;
    const int nwords = (vocab + 1) >> 1;

    // --- index-width autodetect (int64 vs int32 token buffer) ---
    const int* xi = (const int*)xv;
    const bool is64 = (xi[1] == 0) & (xi[3] == 0) & (xi[5] == 0) & (xi[7] == 0);
    const long long* x64 = (const long long*)xv + (size_t)row * seq;
    const int*       x32 = xi + (size_t)row * seq;

    // 1) zero the smem histogram
    for (int w = tid; w < nwords; w += NTHREADS)
        s_cnt[w] = 0u;
    __syncthreads();

    // 2) histogram (u16-packed; counts <= seq < 2^16, no cross-half carry)
    //    + gather idf for the normalizer
    float partial = 0.0f;
    for (int s = tid; s < seq; s += NTHREADS) {
        int tok = is64 ? (int)x64[s] : x32[s];
        atomicAdd(&s_cnt[tok >> 1], 1u << ((tok & 1) * 16));
        partial += __ldg(idf + tok);
    }

    // 3) DENSE zero-fill of the full output row — pure stores, float4 body.
    //    vocab is odd so row base alignment rotates; peel to 16B alignment.
    float* orow = out + (size_t)row * vocab;
    {
        const int mis  = (int)(((size_t)orow >> 2) & 3);   // element misalign
        int peel = (4 - mis) & 3;
        if (peel > vocab) peel = vocab;
        for (int v = tid; v < peel; v += NTHREADS)
            orow[v] = 0.0f;
        const int nb4 = (vocab - peel) >> 2;
        float4* o4 = (float4*)(orow + peel);
        const float4 z4 = make_float4(0.f, 0.f, 0.f, 0.f);
        for (int i = tid; i < nb4; i += NTHREADS)
            o4[i] = z4;
        for (int v = peel + (nb4 << 2) + tid; v < vocab; v += NTHREADS)
            orow[v] = 0.0f;
    }

    // 4) barrier: orders histogram (smem) AND the zero stores (global) for
    //    the whole block before the sparse overwrite.
    __syncthreads();

    // 5) block reduction -> inv_n
    __shared__ float red[NTHREADS / 32];
    __shared__ float inv_n_sh;
    float ws = warp_reduce_sum(partial);
    const int lane = tid & 31;
    const int warp = tid >> 5;
    if (lane == 0) red[warp] = ws;
    __syncthreads();
    if (warp == 0) {
        float v = (lane < (NTHREADS / 32)) ? red[lane] : 0.0f;
        v = warp_reduce_sum(v);
        if (lane == 0) inv_n_sh = 1.0f / v;
    }
    __syncthreads();
    const float inv_n = inv_n_sh;

    // 6) SPARSE overwrite: one store per token occurrence; duplicates write
    //    identical values (idempotent). Token words are L1/L2-hot; idf
    //    gathers hit L2.
    for (int s = tid; s < seq; s += NTHREADS) {
        int tok = is64 ? (int)x64[s] : x32[s];
        unsigned int pair = s_cnt[tok >> 1];
        unsigned int cnt  = (tok & 1) ? (pair >> 16) : (pair & 0xFFFFu);
        orow[tok] = (float)cnt * __ldg(idf + tok) * inv_n;
    }
}

extern "C" void kernel_launch(void* const* d_in, const int* in_sizes, int n_in,
                              void* d_out, int out_size) {
    (void)n_in;
    const void*  x   = d_in[0];                 // (B, S) tokens
    const float* idf = (const float*)d_in[1];   // (V,) fp32
    float*       out = (float*)d_out;           // (B, V) fp32

    const int vocab = in_sizes[1];              // V
    const int batch = out_size / vocab;         // B
    const int seq   = in_sizes[0] / batch;      // S

    const int smem_bytes = ((vocab + 1) / 2) * (int)sizeof(unsigned int);

    static int attr_done = 0;
    if (!attr_done) {
        cudaFuncSetAttribute(tfidf_sparse,
                             cudaFuncAttributeMaxDynamicSharedMemorySize,
                             smem_bytes);
        attr_done = 1;
    }

    tfidf_sparse<<<batch, NTHREADS, smem_bytes, 0>>>(x, idf, out, seq, vocab);
}

// round 15
// speedup vs baseline: 1.0117x; 1.0107x over previous
#include <cuda_runtime.h>
#include <cuda_bf16.h>
#include <stdint.h>

// Problem:
//   x:   (B, S) token ids in [0, V)   (B=512, S=1024, V=50257)
//   idf: (V,) fp32
//   out: (B, V) fp32 = (tf * idf) / rowsum(tf * idf)
//
// R15 design:
//   - rowsum(tf*idf) = sum_s idf[x[row,s]]  -> tiny per-row norm kernel
//     writing 1/n into __device__ g_inv_n[] (no histogram anywhere).
//   - driver memset (best zero-filler, ~5.5 TB/s) CHUNKED over row ranges
//     on stream sM; scatter chunks on stream sS overlap memset of later
//     chunks (event fork/join inside graph capture).
//   - scatter: ONE THREAD PER TOKEN (B*S threads), atomicAdd of
//     idf[tok]*inv_n — duplicates accumulate to cnt*idf*inv_n naturally.
//     REDG-class no-return atomics to mostly-distinct addresses.

#define NTH 256
#define NCHUNK 4
#define MAX_B 4096

__device__ float g_inv_n[MAX_B];

__inline__ __device__ float warp_reduce_sum(float v) {
    #pragma unroll
    for (int o = 16; o > 0; o >>= 1)
        v += __shfl_xor_sync(0xffffffffu, v, o);
    return v;
}

__inline__ __device__ bool detect_i64(const int* xi) {
    // little-endian int64 < 2^31 has zero high words at odd 32-bit indices;
    // P[4 real int32 tokens all == 0] ~ (1/50257)^4 — negligible.
    return (xi[1] == 0) & (xi[3] == 0) & (xi[5] == 0) & (xi[7] == 0);
}

__global__ __launch_bounds__(NTH)
void row_norm_kernel(const void* __restrict__ xv,
                     const float* __restrict__ idf, int seq) {
    const int row = blockIdx.x;
    const int tid = threadIdx.x;
    const int* xi = (const int*)xv;
    const bool is64 = detect_i64(xi);
    const long long* x64 = (const long long*)xv + (size_t)row * seq;
    const int*       x32 = xi + (size_t)row * seq;

    float partial = 0.0f;
    for (int s = tid; s < seq; s += NTH) {
        int tok = is64 ? (int)x64[s] : x32[s];
        partial += __ldg(idf + tok);
    }

    __shared__ float red[NTH / 32];
    float ws = warp_reduce_sum(partial);
    const int lane = tid & 31, warp = tid >> 5;
    if (lane == 0) red[warp] = ws;
    __syncthreads();
    if (warp == 0) {
        float v = (lane < (NTH / 32)) ? red[lane] : 0.0f;
        v = warp_reduce_sum(v);
        if (lane == 0) g_inv_n[row] = 1.0f / v;
    }
}

__global__ __launch_bounds__(NTH)
void scatter_kernel(const void* __restrict__ xv,
                    const float* __restrict__ idf,
                    float* __restrict__ out,
                    int row0, int nrows, int seq, int vocab) {
    const int t = blockIdx.x * NTH + threadIdx.x;
    if (t >= nrows * seq) return;
    const int r   = t / seq;           // one div per thread — negligible
    const int s   = t - r * seq;
    const int row = row0 + r;

    const int* xi = (const int*)xv;
    const bool is64 = detect_i64(xi);
    const int tok = is64 ? (int)((const long long*)xv)[(size_t)row * seq + s]
                         : xi[(size_t)row * seq + s];

    // duplicates within a row accumulate: sum over occurrences of
    // idf*inv_n == cnt * idf * inv_n  (exact: identical addends)
    atomicAdd(out + (size_t)row * vocab + tok,
              __ldg(idf + tok) * g_inv_n[row]);
}

extern "C" void kernel_launch(void* const* d_in, const int* in_sizes, int n_in,
                              void* d_out, int out_size) {
    (void)n_in;
    const void*  x   = d_in[0];                 // (B, S) tokens
    const float* idf = (const float*)d_in[1];   // (V,) fp32
    float*       out = (float*)d_out;           // (B, V) fp32

    const int vocab = in_sizes[1];              // V
    const int batch = out_size / vocab;         // B
    const int seq   = in_sizes[0] / batch;      // S

    // one-time stream/event setup — happens on the correctness call,
    // OUTSIDE graph capture (no device-memory allocation involved)
    static bool init = false;
    static cudaStream_t sM, sS;
    static cudaEvent_t evFork, evM[NCHUNK], evJoinM, evJoinS;
    if (!init) {
        cudaStreamCreateWithFlags(&sM, cudaStreamNonBlocking);
        cudaStreamCreateWithFlags(&sS, cudaStreamNonBlocking);
        cudaEventCreateWithFlags(&evFork, cudaEventDisableTiming);
        for (int c = 0; c < NCHUNK; c++)
            cudaEventCreateWithFlags(&evM[c], cudaEventDisableTiming);
        cudaEventCreateWithFlags(&evJoinM, cudaEventDisableTiming);
        cudaEventCreateWithFlags(&evJoinS, cudaEventDisableTiming);
        init = true;
    }

    // fork both worker streams off the launch stream
    cudaEventRecord(evFork, 0);
    cudaStreamWaitEvent(sM, evFork, 0);
    cudaStreamWaitEvent(sS, evFork, 0);

    // row normalizers on sS (overlaps memset chunk 0)
    row_norm_kernel<<<batch, NTH, 0, sS>>>(x, idf, seq);

    // chunked zero-fill on sM; scatter chunk c on sS waits on memset chunk c
    const int rpc = (batch + NCHUNK - 1) / NCHUNK;   // rows per chunk
    for (int c = 0; c < NCHUNK; c++) {
        const int row0  = c * rpc;
        const int nrows = (row0 + rpc <= batch) ? rpc : (batch - row0);
        if (nrows <= 0) break;
        cudaMemsetAsync(out + (size_t)row0 * vocab, 0,
                        (size_t)nrows * vocab * sizeof(float), sM);
        cudaEventRecord(evM[c], sM);
        cudaStreamWaitEvent(sS, evM[c], 0);
        const int tot = nrows * seq;
        scatter_kernel<<<(tot + NTH - 1) / NTH, NTH, 0, sS>>>(
            x, idf, out, row0, nrows, seq, vocab);
    }

    // join both streams back to the launch stream
    cudaEventRecord(evJoinM, sM);
    cudaEventRecord(evJoinS, sS);
    cudaStreamWaitEvent(0, evJoinM, 0);
    cudaStreamWaitEvent(0, evJoinS, 0);
}